// round 5
// baseline (speedup 1.0000x reference)
#include <cuda_runtime.h>
#include <cstdint>

#define B_    2
#define H_    512
#define W_    512
#define NIN_  64
#define NOUT_ 64
#define NNZ_  131072
#define NMASK_ 131072
#define PTS_PER_CTA 64

// 2 MB mask scratch (allowed: __device__ global, no runtime alloc)
__device__ float g_mask[B_ * H_ * W_];
__device__ int   g_is64;

typedef unsigned long long u64;

// ---------------------------------------------------------------------------
// Packed fp32x2 helpers (Blackwell sm_100+). One FFMA2 = 2 fp32 FMAs/lane.
// ---------------------------------------------------------------------------
__device__ __forceinline__ u64 ffma2(u64 a, u64 b, u64 c) {
    u64 d;
    asm("fma.rn.f32x2 %0, %1, %2, %3;" : "=l"(d) : "l"(a), "l"(b), "l"(c));
    return d;
}
__device__ __forceinline__ u64 pack2_dup(float x) {
    u64 r;
    asm("mov.b64 %0, {%1, %1};" : "=l"(r) : "f"(x));
    return r;
}
__device__ __forceinline__ void unpack2(u64 v, float& lo, float& hi) {
    asm("mov.b64 {%0, %1}, %2;" : "=f"(lo), "=f"(hi) : "l"(v));
}

// ---------------------------------------------------------------------------
// Detect whether the index tensors are int64 or int32 (deterministic).
// ---------------------------------------------------------------------------
__global__ void detect_idx_dtype_kernel(const unsigned int* __restrict__ w) {
    __shared__ int any_nonzero;
    if (threadIdx.x == 0) any_nonzero = 0;
    __syncthreads();
    unsigned int v = w[threadIdx.x * 2 + 1];   // first 64 odd words
    if (v != 0u) atomicOr(&any_nonzero, 1);
    __syncthreads();
    if (threadIdx.x == 0) g_is64 = (any_nonzero == 0) ? 1 : 0;
}

__device__ __forceinline__ int3 load_triplet(const void* p, int i, int is64) {
    if (is64) {
        const long long* q = (const long long*)p;
        return make_int3((int)q[3 * i], (int)q[3 * i + 1], (int)q[3 * i + 2]);
    } else {
        const int* q = (const int*)p;
        return make_int3(q[3 * i], q[3 * i + 1], q[3 * i + 2]);
    }
}

// ---------------------------------------------------------------------------
// Mask scatter: g_mask[b,y,x] += mask_values[i]
// ---------------------------------------------------------------------------
__global__ void mask_scatter_kernel(const void* __restrict__ mask_idx,
                                    const float* __restrict__ mask_vals) {
    int i = blockIdx.x * blockDim.x + threadIdx.x;
    if (i >= NMASK_) return;
    int is64 = g_is64;
    int3 t = load_triplet(mask_idx, i, is64);
    atomicAdd(&g_mask[(t.x * H_ + t.y) * W_ + t.z], mask_vals[i]);
}

// ---------------------------------------------------------------------------
// Vectorized global reduction add (sm_90+ PTX)
// ---------------------------------------------------------------------------
__device__ __forceinline__ void red_add_v4(float* p, float4 v) {
    asm volatile("red.global.add.v4.f32 [%0], {%1, %2, %3, %4};"
                 :: "l"(p), "f"(v.x), "f"(v.y), "f"(v.z), "f"(v.w)
                 : "memory");
}

// ---------------------------------------------------------------------------
// Main sparse conv: grid = (NNZ/64, 3[ky]), block = 256.
// Each thread: 4 points x 4 channels x 3 kx-taps = 48 FMA = 24 FFMA2 / k-iter.
// SMEM: weights[3][64][64] (48KB) + valuesT[64][68] (17KB) + idx[64][3]
// ---------------------------------------------------------------------------
__global__ void conv_scatter_kernel(const float* __restrict__ values,
                                    const float* __restrict__ kern,
                                    const void*  __restrict__ indices,
                                    float* __restrict__ out) {
    extern __shared__ float smem[];
    float* sW = smem;                        // [kx][k][c] : 3*64*64
    float* sV = smem + 3 * 64 * 64;          // [k][p] padded rows of 68
    int*   sI = (int*)(sV + 64 * 68);        // [p][3] : b, sy(clipped), ix

    const int t  = threadIdx.x;
    const int ky = blockIdx.y;

    // Stage weights for this ky: 12288 floats = 3072 float4, 256 threads
    {
        const float4* gW = (const float4*)(kern + (size_t)ky * 3 * 64 * 64);
        float4* sW4 = (float4*)sW;
        #pragma unroll
        for (int r = 0; r < 12; r++) sW4[r * 256 + t] = gW[r * 256 + t];
    }

    const int gp0 = blockIdx.x * PTS_PER_CTA;

    // Stage values transposed: sV[k][p] (pad 68 keeps 16B alignment of rows)
    #pragma unroll
    for (int r = 0; r < 4; r++) {
        int li = r * 1024 + t * 4;            // flat offset into 64x64 tile
        int p = li >> 6, k = li & 63;
        float4 v = *(const float4*)(values + (size_t)gp0 * 64 + li);
        sV[(k + 0) * 68 + p] = v.x;
        sV[(k + 1) * 68 + p] = v.y;
        sV[(k + 2) * 68 + p] = v.z;
        sV[(k + 3) * 68 + p] = v.w;
    }

    // Stage indices with ky-row clip precomputed
    if (t < PTS_PER_CTA) {
        int is64 = g_is64;
        int3 tr = load_triplet(indices, gp0 + t, is64);
        int sy = tr.y + ky - 1;
        sy = min(max(sy, 0), H_ - 1);
        sI[t * 3 + 0] = tr.x;
        sI[t * 3 + 1] = sy;
        sI[t * 3 + 2] = tr.z;
    }
    __syncthreads();

    const int c4 = (t & 15) * 4;        // channel quad
    const int pb = (t >> 4) * 4;        // point quad base

    // acc[j][kx][half]: half 0 = channels (c4,c4+1), half 1 = (c4+2,c4+3)
    u64 acc[4][3][2];
    #pragma unroll
    for (int j = 0; j < 4; j++)
        #pragma unroll
        for (int kx = 0; kx < 3; kx++) {
            acc[j][kx][0] = 0ull;
            acc[j][kx][1] = 0ull;
        }

    #pragma unroll 4
    for (int k = 0; k < 64; k++) {
        float4 v = *(float4*)&sV[k * 68 + pb];
        ulonglong2 w0 = *(ulonglong2*)&sW[(0 * 64 + k) * 64 + c4];
        ulonglong2 w1 = *(ulonglong2*)&sW[(1 * 64 + k) * 64 + c4];
        ulonglong2 w2 = *(ulonglong2*)&sW[(2 * 64 + k) * 64 + c4];
        float vv[4] = {v.x, v.y, v.z, v.w};
        #pragma unroll
        for (int j = 0; j < 4; j++) {
            u64 vj = pack2_dup(vv[j]);
            acc[j][0][0] = ffma2(vj, w0.x, acc[j][0][0]);
            acc[j][0][1] = ffma2(vj, w0.y, acc[j][0][1]);
            acc[j][1][0] = ffma2(vj, w1.x, acc[j][1][0]);
            acc[j][1][1] = ffma2(vj, w1.y, acc[j][1][1]);
            acc[j][2][0] = ffma2(vj, w2.x, acc[j][2][0]);
            acc[j][2][1] = ffma2(vj, w2.y, acc[j][2][1]);
        }
    }

    // Scatter: 3 taps x 4 points, red.v4 per channel quad
    #pragma unroll
    for (int j = 0; j < 4; j++) {
        int p  = pb + j;
        int b  = sI[p * 3 + 0];
        int sy = sI[p * 3 + 1];
        int ix = sI[p * 3 + 2];
        int rowbase = (b * H_ + sy) * W_;
        #pragma unroll
        for (int kx = 0; kx < 3; kx++) {
            int sx = ix + kx - 1;
            sx = min(max(sx, 0), W_ - 1);
            float* dst = out + ((size_t)(rowbase + sx) * NOUT_ + c4);
            float4 a;
            unpack2(acc[j][kx][0], a.x, a.y);
            unpack2(acc[j][kx][1], a.z, a.w);
            red_add_v4(dst, a);
        }
    }
}

// ---------------------------------------------------------------------------
// Epilogue: out = (dense + mask*bias) * mask.
// Only ~22% of pixels have nonzero mask: skip the dense read where m == 0
// (result is 0 there regardless), write unconditionally.
// ---------------------------------------------------------------------------
__global__ void finalize_kernel(float* __restrict__ out,
                                const float* __restrict__ bias) {
    int i = blockIdx.x * blockDim.x + threadIdx.x;   // float4 index
    int pix = i >> 4;
    int c4  = (i & 15) * 4;
    float m = g_mask[pix];
    float4 o = make_float4(0.f, 0.f, 0.f, 0.f);
    if (m != 0.f) {
        o = ((float4*)out)[i];
        float4 bb = *(const float4*)(bias + c4);
        o.x = (o.x + m * bb.x) * m;
        o.y = (o.y + m * bb.y) * m;
        o.z = (o.z + m * bb.z) * m;
        o.w = (o.w + m * bb.w) * m;
    }
    ((float4*)out)[i] = o;
}

// ---------------------------------------------------------------------------
extern "C" void kernel_launch(void* const* d_in, const int* in_sizes, int n_in,
                              void* d_out, int out_size) {
    const float* values    = (const float*)d_in[0];
    const float* kern      = (const float*)d_in[1];
    const float* bias      = (const float*)d_in[2];
    const float* mask_vals = (const float*)d_in[3];
    const void*  indices   = d_in[4];
    const void*  mask_idx  = d_in[5];
    float* out = (float*)d_out;

    void* maskPtr = nullptr;
    cudaGetSymbolAddress(&maskPtr, g_mask);

    size_t smem = (3 * 64 * 64 + 64 * 68) * sizeof(float) + 64 * 3 * sizeof(int);
    cudaFuncSetAttribute(conv_scatter_kernel,
                         cudaFuncAttributeMaxDynamicSharedMemorySize, (int)smem);

    cudaMemsetAsync(out, 0, (size_t)out_size * sizeof(float), 0);
    cudaMemsetAsync(maskPtr, 0, sizeof(float) * B_ * H_ * W_, 0);

    detect_idx_dtype_kernel<<<1, 64>>>((const unsigned int*)indices);
    mask_scatter_kernel<<<NMASK_ / 256, 256>>>(mask_idx, mask_vals);
    conv_scatter_kernel<<<dim3(NNZ_ / PTS_PER_CTA, 3), 256, smem>>>(
        values, kern, indices, out);
    finalize_kernel<<<(B_ * H_ * W_ * (NOUT_ / 4)) / 256, 256>>>(out, bias);
}

// round 8
// speedup vs baseline: 1.2939x; 1.2939x over previous
#include <cuda_runtime.h>
#include <cstdint>

#define B_    2
#define H_    512
#define W_    512
#define NNZ_  131072
#define NMASK_ 131072
#define TILE_PTS 128

// ---------------------------------------------------------------------------
// Static device scratch (no runtime allocation)
// ---------------------------------------------------------------------------
__device__ float g_mask[B_ * H_ * W_];
__device__ int   g_is64;
// Pre-packed tf32 B fragments: [ky][pass hi/lo][ntile 24][ks 8][lane 32][2]
// = 3 * 2 * 12288 floats
__device__ float g_Bf[3 * 24576];

// ---------------------------------------------------------------------------
// Helpers
// ---------------------------------------------------------------------------
__device__ __forceinline__ uint32_t tf32_hi_bits(float v) {
    uint32_t u;
    asm("cvt.rna.tf32.f32 %0, %1;" : "=r"(u) : "f"(v));
    return u;
}

__device__ __forceinline__ void mma_tf32(float* acc, uint32_t a0, uint32_t a1,
                                         uint32_t a2, uint32_t a3,
                                         uint32_t b0, uint32_t b1) {
    asm volatile(
        "mma.sync.aligned.m16n8k8.row.col.f32.tf32.tf32.f32 "
        "{%0,%1,%2,%3}, {%4,%5,%6,%7}, {%8,%9}, {%0,%1,%2,%3};"
        : "+f"(acc[0]), "+f"(acc[1]), "+f"(acc[2]), "+f"(acc[3])
        : "r"(a0), "r"(a1), "r"(a2), "r"(a3), "r"(b0), "r"(b1));
}

__device__ __forceinline__ void red_add_v2(float* p, float x, float y) {
    asm volatile("red.global.add.v2.f32 [%0], {%1, %2};"
                 :: "l"(p), "f"(x), "f"(y) : "memory");
}
__device__ __forceinline__ void red_add_v4(float* p, float4 v) {
    asm volatile("red.global.add.v4.f32 [%0], {%1, %2, %3, %4};"
                 :: "l"(p), "f"(v.x), "f"(v.y), "f"(v.z), "f"(v.w)
                 : "memory");
}

// ---------------------------------------------------------------------------
// Index dtype detection (int64 vs int32), deterministic
// ---------------------------------------------------------------------------
__global__ void detect_idx_dtype_kernel(const unsigned int* __restrict__ w) {
    __shared__ int any_nonzero;
    if (threadIdx.x == 0) any_nonzero = 0;
    __syncthreads();
    unsigned int v = w[threadIdx.x * 2 + 1];
    if (v != 0u) atomicOr(&any_nonzero, 1);
    __syncthreads();
    if (threadIdx.x == 0) g_is64 = (any_nonzero == 0) ? 1 : 0;
}

__device__ __forceinline__ int3 load_triplet(const void* p, int i, int is64) {
    if (is64) {
        const long long* q = (const long long*)p;
        return make_int3((int)q[3 * i], (int)q[3 * i + 1], (int)q[3 * i + 2]);
    } else {
        const int* q = (const int*)p;
        return make_int3(q[3 * i], q[3 * i + 1], q[3 * i + 2]);
    }
}

// ---------------------------------------------------------------------------
// Weight prep: kernel[ky][kx][k][c] -> per-lane tf32 B fragments (hi & lo)
// Fragment (m16n8k8 row.col): b0: k=lane&3,       n=lane>>2
//                             b1: k=(lane&3)+4,   n=lane>>2
// Element (NT, ks, lane, e): n = NT*8 + (lane>>2), k = ks*8 + (lane&3) + e*4
// Float offset within a ky block: pass*12288 + ((NT*8+ks)*64 + lane*2 + e)
// ---------------------------------------------------------------------------
__global__ void weights_prep_kernel(const float* __restrict__ kern) {
    int ky = blockIdx.x;
    float* dst = g_Bf + ky * 24576;
    for (int idx = threadIdx.x; idx < 12288; idx += blockDim.x) {
        int e    = idx & 1;
        int lane = (idx >> 1) & 31;
        int ks   = (idx >> 6) & 7;
        int NT   = idx >> 9;
        int n = NT * 8 + (lane >> 2);
        int k = ks * 8 + (lane & 3) + e * 4;
        int kx = n >> 6, c = n & 63;
        float v = kern[(((ky * 3) + kx) * 64 + k) * 64 + c];
        uint32_t hib = tf32_hi_bits(v);
        float hif = __uint_as_float(hib);
        uint32_t lob = tf32_hi_bits(v - hif);
        int off = (NT * 8 + ks) * 64 + lane * 2 + e;
        dst[off]         = __uint_as_float(hib);
        dst[12288 + off] = __uint_as_float(lob);
    }
}

// ---------------------------------------------------------------------------
// Mask scatter
// ---------------------------------------------------------------------------
__global__ void mask_scatter_kernel(const void* __restrict__ mask_idx,
                                    const float* __restrict__ mask_vals) {
    int i = blockIdx.x * blockDim.x + threadIdx.x;
    if (i >= NMASK_) return;
    int3 t = load_triplet(mask_idx, i, g_is64);
    atomicAdd(&g_mask[(t.x * H_ + t.y) * W_ + t.z], mask_vals[i]);
}

// ---------------------------------------------------------------------------
// Main conv via mma.sync tf32 (3x split).
// grid = 1024 CTAs (128 pts each), 256 threads (8 warps).
// Warp w: rowhalf = w&1 (64 rows), n-group = w>>1 (6 n-tiles of 8).
// Per ky: D[128,192] = V[128,64] @ B(ky)^T, scattered with red.v2.
// SMEM: B fragments [2 pass][24 NT][8 ks][32 lane][2] floats (96KB) + sI[128][3]
// ---------------------------------------------------------------------------
__global__ void __launch_bounds__(256, 1)
conv_mma_kernel(const float* __restrict__ values,
                const void*  __restrict__ indices,
                float* __restrict__ out) {
    extern __shared__ float smem[];
    float* sB = smem;                 // 24576 floats
    int*   sI = (int*)(smem + 24576); // 128*3 ints

    const int t = threadIdx.x;
    const int w = t >> 5;
    const int lane = t & 31;
    const int rowhalf = w & 1;        // 0/1 -> rows 0-63 / 64-127
    const int ng = w >> 1;            // 0..3 -> n-tiles ng*6 .. ng*6+5

    const int gp0 = blockIdx.x * TILE_PTS;

    if (t < TILE_PTS) {
        int3 tr = load_triplet(indices, gp0 + t, g_is64);
        sI[t * 3 + 0] = tr.x;
        sI[t * 3 + 1] = tr.y;
        sI[t * 3 + 2] = tr.z;
    }

    // Base pointer for this warp's A rows: a0 row = rowhalf*64 + i*16 + lane>>2
    const float* vbase = values + (size_t)(gp0 + rowhalf * 64 + (lane >> 2)) * 64
                                + (lane & 3);

    float acc[4][6][4];

    for (int ky = 0; ky < 3; ky++) {
        __syncthreads();   // sI ready (ky=0) / prev-ky B reads done
        // Stage B(ky): linear copy of 6144 float4
        {
            const float4* gB = (const float4*)(g_Bf + ky * 24576);
            float4* sB4 = (float4*)sB;
            #pragma unroll
            for (int r = 0; r < 24; r++) sB4[r * 256 + t] = gB[r * 256 + t];
        }
        __syncthreads();

        #pragma unroll
        for (int i = 0; i < 4; i++)
            #pragma unroll
            for (int nt = 0; nt < 6; nt++)
                #pragma unroll
                for (int j = 0; j < 4; j++) acc[i][nt][j] = 0.f;

        #pragma unroll 2
        for (int ks = 0; ks < 8; ks++) {
            // A fragments for 4 rowblocks, tf32 hi/lo on the fly
            uint32_t ahi[4][4], alo[4][4];
            #pragma unroll
            for (int i = 0; i < 4; i++) {
                const float* p = vbase + (size_t)i * 16 * 64 + ks * 8;
                float v0 = p[0];            // (r, c)
                float v1 = p[8 * 64];       // (r+8, c)
                float v2 = p[4];            // (r, c+4)
                float v3 = p[8 * 64 + 4];   // (r+8, c+4)
                ahi[i][0] = tf32_hi_bits(v0);
                ahi[i][1] = tf32_hi_bits(v1);
                ahi[i][2] = tf32_hi_bits(v2);
                ahi[i][3] = tf32_hi_bits(v3);
                alo[i][0] = tf32_hi_bits(v0 - __uint_as_float(ahi[i][0]));
                alo[i][1] = tf32_hi_bits(v1 - __uint_as_float(ahi[i][1]));
                alo[i][2] = tf32_hi_bits(v2 - __uint_as_float(ahi[i][2]));
                alo[i][3] = tf32_hi_bits(v3 - __uint_as_float(ahi[i][3]));
            }
            #pragma unroll
            for (int nt = 0; nt < 6; nt++) {
                int NT = ng * 6 + nt;
                const float* bp = sB + (NT * 8 + ks) * 64 + lane * 2;
                uint2 bh = *(const uint2*)bp;            // pass 0 (hi)
                uint2 bl = *(const uint2*)(bp + 12288);  // pass 1 (lo)
                #pragma unroll
                for (int i = 0; i < 4; i++) {
                    mma_tf32(acc[i][nt], ahi[i][0], ahi[i][1], ahi[i][2], ahi[i][3], bh.x, bh.y);
                    mma_tf32(acc[i][nt], alo[i][0], alo[i][1], alo[i][2], alo[i][3], bh.x, bh.y);
                    mma_tf32(acc[i][nt], ahi[i][0], ahi[i][1], ahi[i][2], ahi[i][3], bl.x, bl.y);
                }
            }
        }

        // Scatter: d0/d1 = (r0, n0/n0+1), d2/d3 = (r0+8, n0/n0+1)
        #pragma unroll
        for (int i = 0; i < 4; i++) {
            int r0 = rowhalf * 64 + i * 16 + (lane >> 2);
            int r1 = r0 + 8;
            int b0 = sI[r0 * 3 + 0], y0 = sI[r0 * 3 + 1], x0 = sI[r0 * 3 + 2];
            int b1 = sI[r1 * 3 + 0], y1 = sI[r1 * 3 + 1], x1 = sI[r1 * 3 + 2];
            int sy0 = min(max(y0 + ky - 1, 0), H_ - 1);
            int sy1 = min(max(y1 + ky - 1, 0), H_ - 1);
            int base0 = (b0 * H_ + sy0) * W_;
            int base1 = (b1 * H_ + sy1) * W_;
            #pragma unroll
            for (int nt = 0; nt < 6; nt++) {
                int n0 = (ng * 6 + nt) * 8 + (lane & 3) * 2;
                int kx = n0 >> 6, c = n0 & 63;
                int sx0 = min(max(x0 + kx - 1, 0), W_ - 1);
                int sx1 = min(max(x1 + kx - 1, 0), W_ - 1);
                red_add_v2(out + (size_t)(base0 + sx0) * 64 + c,
                           acc[i][nt][0], acc[i][nt][1]);
                red_add_v2(out + (size_t)(base1 + sx1) * 64 + c,
                           acc[i][nt][2], acc[i][nt][3]);
            }
        }
    }
}

// ---------------------------------------------------------------------------
// Epilogue: out = (dense + mask*bias) * mask  (unconditional, streaming)
// ---------------------------------------------------------------------------
__global__ void finalize_kernel(float* __restrict__ out,
                                const float* __restrict__ bias) {
    int i = blockIdx.x * blockDim.x + threadIdx.x;
    int pix = i >> 4;
    int c4  = (i & 15) * 4;
    float m = g_mask[pix];
    float4 o = ((float4*)out)[i];
    float4 bb = *(const float4*)(bias + c4);
    o.x = (o.x + m * bb.x) * m;
    o.y = (o.y + m * bb.y) * m;
    o.z = (o.z + m * bb.z) * m;
    o.w = (o.w + m * bb.w) * m;
    ((float4*)out)[i] = o;
}

// ---------------------------------------------------------------------------
extern "C" void kernel_launch(void* const* d_in, const int* in_sizes, int n_in,
                              void* d_out, int out_size) {
    const float* values    = (const float*)d_in[0];
    const float* kern      = (const float*)d_in[1];
    const float* bias      = (const float*)d_in[2];
    const float* mask_vals = (const float*)d_in[3];
    const void*  indices   = d_in[4];
    const void*  mask_idx  = d_in[5];
    float* out = (float*)d_out;

    void* maskPtr = nullptr;
    cudaGetSymbolAddress(&maskPtr, g_mask);

    size_t smem = 24576 * sizeof(float) + 128 * 3 * sizeof(int);
    cudaFuncSetAttribute(conv_mma_kernel,
                         cudaFuncAttributeMaxDynamicSharedMemorySize, (int)smem);

    cudaMemsetAsync(out, 0, (size_t)out_size * sizeof(float), 0);
    cudaMemsetAsync(maskPtr, 0, sizeof(float) * B_ * H_ * W_, 0);

    detect_idx_dtype_kernel<<<1, 64>>>((const unsigned int*)indices);
    weights_prep_kernel<<<3, 256>>>(kern);
    mask_scatter_kernel<<<NMASK_ / 256, 256>>>(mask_idx, mask_vals);
    conv_mma_kernel<<<NNZ_ / TILE_PTS, 256, smem>>>(values, indices, out);
    finalize_kernel<<<(B_ * H_ * W_ * 16) / 256, 256>>>(out, bias);
}